// round 16
// baseline (speedup 1.0000x reference)
#include <cuda_runtime.h>
#include <cuda_bf16.h>
#include <cstdint>

constexpr int NPIX = 4096;
#define DEVI static __device__ __forceinline__

// bf16 scratch: q[B,N,32] (pre-scaled by log2e), k[B,N,32], v CHANNEL-MAJOR [B,256,N]
__device__ __nv_bfloat16 g_q[(size_t)4 * 4096 * 32];
__device__ __nv_bfloat16 g_k[(size_t)4 * 4096 * 32];
__device__ __nv_bfloat16 g_v[(size_t)4 * 256 * 4096];

DEVI uint32_t su(const void* p) { return (uint32_t)__cvta_generic_to_shared(p); }
DEVI void ldsm4(uint32_t& r0, uint32_t& r1, uint32_t& r2, uint32_t& r3, uint32_t a) {
    asm volatile("ldmatrix.sync.aligned.m8n8.x4.shared.b16 {%0,%1,%2,%3},[%4];"
                 : "=r"(r0), "=r"(r1), "=r"(r2), "=r"(r3) : "r"(a));
}
DEVI void ldsm4t(uint32_t& r0, uint32_t& r1, uint32_t& r2, uint32_t& r3, uint32_t a) {
    asm volatile("ldmatrix.sync.aligned.m8n8.x4.trans.shared.b16 {%0,%1,%2,%3},[%4];"
                 : "=r"(r0), "=r"(r1), "=r"(r2), "=r"(r3) : "r"(a));
}
DEVI void mma16816(float* c, const uint32_t* a, uint32_t b0, uint32_t b1) {
    asm volatile("mma.sync.aligned.m16n8k16.row.col.f32.bf16.bf16.f32 "
                 "{%0,%1,%2,%3},{%4,%5,%6,%7},{%8,%9},{%0,%1,%2,%3};"
                 : "+f"(c[0]), "+f"(c[1]), "+f"(c[2]), "+f"(c[3])
                 : "r"(a[0]), "r"(a[1]), "r"(a[2]), "r"(a[3]), "r"(b0), "r"(b1));
}
DEVI void cp16(uint32_t s, const void* g) {
    asm volatile("cp.async.cg.shared.global [%0],[%1],16;" ::"r"(s), "l"(g));
}
DEVI void cp_commit() { asm volatile("cp.async.commit_group;" ::: "memory"); }
template <int NN> DEVI void cp_wait() { asm volatile("cp.async.wait_group %0;" ::"n"(NN) : "memory"); }
DEVI float ex2f(float x) { float r; asm("ex2.approx.f32 %0,%1;" : "=f"(r) : "f"(x)); return r; }
DEVI uint32_t packbf2(float a, float b) {
    __nv_bfloat162 h = __floats2bfloat162_rn(a, b);
    return *reinterpret_cast<uint32_t*>(&h);
}
DEVI void bar384() { asm volatile("bar.sync 1, 384;" ::: "memory"); }

// ===========================================================================
// Projection, 256 threads / 8 warps (round-13 structure, inline weight
// conversion instead of prep kernel). block = (m-tile 128, batch).
// Writes q (log2e-scaled) / k row-major, v CHANNEL-MAJOR via smem transpose.
// smem: Xc[64][136], Ac[64][136], Wv[256][72], Wq[32][72], Wk[32][72]
// ===========================================================================
constexpr int PROJ_SMEM = (64 * 136 * 2) * 2 + 256 * 72 * 2 + 32 * 72 * 2 * 2;  // 80896

__global__ __launch_bounds__(256, 1) void proj_kernel(
    const float* __restrict__ ef, const float* __restrict__ sf, const float* __restrict__ attn,
    const float* __restrict__ Qw, const float* __restrict__ Qb,
    const float* __restrict__ Kw, const float* __restrict__ Kb,
    const float* __restrict__ Vw, const float* __restrict__ Vb)
{
    extern __shared__ __align__(16) char smem_raw[];
    __nv_bfloat16* Xc = (__nv_bfloat16*)smem_raw;
    __nv_bfloat16* Ac = Xc + 64 * 136;
    __nv_bfloat16* Wv = Ac + 64 * 136;
    __nv_bfloat16* Wq = Wv + 256 * 72;
    __nv_bfloat16* Wk = Wq + 32 * 72;

    const int b = blockIdx.y, m0 = blockIdx.x * 128;
    const int tid = threadIdx.x, lane = tid & 31, warp = tid >> 5, mw = warp * 16;
    const float L = 1.4426950408889634f;

    float ov[128], oq[16], ok[16];
#pragma unroll
    for (int i = 0; i < 128; i++) ov[i] = 0.f;
#pragma unroll
    for (int i = 0; i < 16; i++) { oq[i] = 0.f; ok[i] = 0.f; }

#pragma unroll 1
    for (int ic = 0; ic < 8; ic++) {
        const int i0 = ic * 64;
        __syncthreads();
        // ---- weights fp32 -> bf16 smem (inline conversion, no prep) ----
#pragma unroll
        for (int t = 0; t < 16; t++) {          // Vw chunk: 256 rows x 16 float4
            int idx = tid + t * 256, r = idx >> 4, j4 = (idx & 15) * 4;
            float4 v = *(const float4*)(Vw + (size_t)r * 512 + i0 + j4);
            *(uint2*)(Wv + r * 72 + j4) = make_uint2(packbf2(v.x, v.y), packbf2(v.z, v.w));
        }
        for (int t = tid; t < 32 * 16; t += 256) {   // Qw chunk (log2e-scaled)
            int r = t >> 4, j4 = (t & 15) * 4;
            float4 v = *(const float4*)(Qw + (size_t)r * 512 + i0 + j4);
            *(uint2*)(Wq + r * 72 + j4) =
                make_uint2(packbf2(v.x * L, v.y * L), packbf2(v.z * L, v.w * L));
        }
        if (ic < 4) {
            for (int t = tid; t < 32 * 16; t += 256) {
                int r = t >> 4, j4 = (t & 15) * 4;
                float4 v = *(const float4*)(Kw + (size_t)r * 256 + i0 + j4);
                *(uint2*)(Wk + r * 72 + j4) = make_uint2(packbf2(v.x, v.y), packbf2(v.z, v.w));
            }
        }
        // ---- X chunk [64 i][128 m] fp32 -> bf16 ----
#pragma unroll
        for (int t = 0; t < 8; t++) {
            int idx = tid + t * 256, il = idx >> 5, j = (idx & 31) * 4;
            int gi = i0 + il;
            const float* src = (gi < 256) ? (ef + ((size_t)(b * 256 + gi)) * NPIX + m0 + j)
                                          : (sf + ((size_t)(b * 256 + gi - 256)) * NPIX + m0 + j);
            float4 v = *(const float4*)src;
            *(uint2*)(Xc + il * 136 + j) = make_uint2(packbf2(v.x, v.y), packbf2(v.z, v.w));
        }
        if (ic < 4) {
#pragma unroll
            for (int t = 0; t < 8; t++) {
                int idx = tid + t * 256, il = idx >> 5, j = (idx & 31) * 4;
                float4 v = *(const float4*)(attn + ((size_t)(b * 256 + i0 + il)) * NPIX + m0 + j);
                *(uint2*)(Ac + il * 136 + j) = make_uint2(packbf2(v.x, v.y), packbf2(v.z, v.w));
            }
        }
        __syncthreads();

#pragma unroll
        for (int kt = 0; kt < 4; kt++) {
            const int k0 = kt * 16;
            uint32_t xa[4];
            ldsm4t(xa[0], xa[1], xa[2], xa[3],
                su(Xc + (k0 + (lane & 7) + ((lane >> 4) << 3)) * 136 + mw + (((lane >> 3) & 1) << 3)));
#pragma unroll
            for (int cp = 0; cp < 16; cp++) {
                uint32_t b0, b1, b2, b3;
                ldsm4(b0, b1, b2, b3, su(Wv + ((cp << 4) + (lane & 15)) * 72 + k0 + ((lane >> 4) << 3)));
                mma16816(ov + cp * 8, xa, b0, b2);
                mma16816(ov + cp * 8 + 4, xa, b1, b3);
            }
            {
                uint32_t b0, b1, b2, b3;
                ldsm4(b0, b1, b2, b3, su(Wq + (lane & 15) * 72 + k0 + ((lane >> 4) << 3)));
                mma16816(oq + 0, xa, b0, b2);
                mma16816(oq + 4, xa, b1, b3);
                ldsm4(b0, b1, b2, b3, su(Wq + (16 + (lane & 15)) * 72 + k0 + ((lane >> 4) << 3)));
                mma16816(oq + 8, xa, b0, b2);
                mma16816(oq + 12, xa, b1, b3);
            }
            if (ic < 4) {
                uint32_t aa[4];
                ldsm4t(aa[0], aa[1], aa[2], aa[3],
                    su(Ac + (k0 + (lane & 7) + ((lane >> 4) << 3)) * 136 + mw + (((lane >> 3) & 1) << 3)));
                uint32_t b0, b1, b2, b3;
                ldsm4(b0, b1, b2, b3, su(Wk + (lane & 15) * 72 + k0 + ((lane >> 4) << 3)));
                mma16816(ok + 0, aa, b0, b2);
                mma16816(ok + 4, aa, b1, b3);
                ldsm4(b0, b1, b2, b3, su(Wk + (16 + (lane & 15)) * 72 + k0 + ((lane >> 4) << 3)));
                mma16816(ok + 8, aa, b0, b2);
                mma16816(ok + 12, aa, b1, b3);
            }
        }
    }

    const int r0 = m0 + mw + (lane >> 2), cb = (lane & 3) * 2;
#pragma unroll
    for (int dt = 0; dt < 4; dt++) {
        int d = dt * 8 + cb;
        float bq0 = Qb[d] * L, bq1 = Qb[d + 1] * L;
        *(uint32_t*)&g_q[((size_t)(b * NPIX + r0)) * 32 + d]     = packbf2(oq[dt * 4 + 0] + bq0, oq[dt * 4 + 1] + bq1);
        *(uint32_t*)&g_q[((size_t)(b * NPIX + r0 + 8)) * 32 + d] = packbf2(oq[dt * 4 + 2] + bq0, oq[dt * 4 + 3] + bq1);
        float bk0 = Kb[d], bk1 = Kb[d + 1];
        *(uint32_t*)&g_k[((size_t)(b * NPIX + r0)) * 32 + d]     = packbf2(ok[dt * 4 + 0] + bk0, ok[dt * 4 + 1] + bk1);
        *(uint32_t*)&g_k[((size_t)(b * NPIX + r0 + 8)) * 32 + d] = packbf2(ok[dt * 4 + 2] + bk0, ok[dt * 4 + 3] + bk1);
    }
    // v: transpose through smem -> channel-major g_v[b][c][m]
    __syncthreads();
    __nv_bfloat16* Vt = (__nv_bfloat16*)smem_raw;   // [256][136]
    const int rl = mw + (lane >> 2);
#pragma unroll
    for (int ct = 0; ct < 32; ct++) {
        int c = ct * 8 + cb;
        float bb0 = Vb[c], bb1 = Vb[c + 1];
        Vt[c * 136 + rl]           = __float2bfloat16(ov[ct * 4 + 0] + bb0);
        Vt[(c + 1) * 136 + rl]     = __float2bfloat16(ov[ct * 4 + 1] + bb1);
        Vt[c * 136 + rl + 8]       = __float2bfloat16(ov[ct * 4 + 2] + bb0);
        Vt[(c + 1) * 136 + rl + 8] = __float2bfloat16(ov[ct * 4 + 3] + bb1);
    }
    __syncthreads();
#pragma unroll
    for (int t = 0; t < 16; t++) {
        int i = tid + t * 256;                 // 4096 uint4 = 256 rows x 16
        int c = i >> 4, seg = i & 15;
        *(uint4*)(g_v + ((size_t)(b * 256 + c)) * NPIX + m0 + seg * 8) =
            *(uint4*)(Vt + c * 136 + seg * 8);
    }
}

// ===========================================================================
// Flash attention (round-10 winner, EXACT): warp-specialized HMMA.
// 384 threads: warps 0-3 = S (QK^T + exp2 -> P smem + row sums)
//              warps 4-11 = PV (O[16m x 256ch] fp32 regs)
// smem: Qs[128][40] | Ks[2][64][40] | Vt[3][256][72] | Ps[2][128][72] | Ls[128]
// ===========================================================================
constexpr int FS_Q = 0;
constexpr int FS_K = FS_Q + 128 * 40 * 2;           // 10240
constexpr int FS_V = FS_K + 2 * 64 * 40 * 2;        // 20480
constexpr int FS_P = FS_V + 3 * 256 * 72 * 2;       // 131072
constexpr int FS_L = FS_P + 2 * 128 * 72 * 2;       // 167936
constexpr int FLASH_SMEM = FS_L + 512;              // 168448

__global__ __launch_bounds__(384, 1)
void flash_kernel(const float* __restrict__ ef, const float* __restrict__ gamma_p,
                  float* __restrict__ out)
{
    extern __shared__ __align__(16) char smem[];
    __nv_bfloat16* Qs = (__nv_bfloat16*)(smem + FS_Q);
    __nv_bfloat16* Ks = (__nv_bfloat16*)(smem + FS_K);
    __nv_bfloat16* Vt = (__nv_bfloat16*)(smem + FS_V);
    __nv_bfloat16* Ps = (__nv_bfloat16*)(smem + FS_P);
    float* Ls = (float*)(smem + FS_L);

    const int b = blockIdx.y, m0 = blockIdx.x * 128;
    const int tid = threadIdx.x, lane = tid & 31, warp = tid >> 5;

    const __nv_bfloat16* gq = g_q + (size_t)b * NPIX * 32;
    const __nv_bfloat16* gk = g_k + (size_t)b * NPIX * 32;
    const __nv_bfloat16* gv = g_v + (size_t)b * 256 * NPIX;   // [256][4096]

    // initial loads: Q (full), K(0), V(0)
#pragma unroll
    for (int t = 0; t < 2; t++) {
        int idx = tid + t * 384;
        if (idx < 512) {
            int r = idx >> 2, sg = idx & 3;
            cp16(su(Qs + r * 40 + sg * 8), gq + (size_t)(m0 + r) * 32 + sg * 8);
        }
    }
    if (tid < 256) {
        int r = tid >> 2, sg = tid & 3;
        cp16(su(Ks + r * 40 + sg * 8), gk + (size_t)r * 32 + sg * 8);
    }
#pragma unroll
    for (int t = 0; t < 6; t++) {
        int idx = tid + t * 384;
        if (idx < 2048) {
            int c = idx >> 3, sg = idx & 7;
            cp16(su(Vt + c * 72 + sg * 8), gv + (size_t)c * NPIX + sg * 8);
        }
    }
    cp_commit();

    if (warp < 4) {
        // ------------------- S warps -------------------
        const int mt = warp * 32;
        uint32_t qa[2][2][4];
        float l4[4] = {0.f, 0.f, 0.f, 0.f};
#pragma unroll 1
        for (int nt = 0; nt < 64; nt++) {
            const int buf = nt & 1;
            if (nt + 1 < 64) {
                const int n0 = (nt + 1) * 64, kb = (nt + 1) & 1;
#pragma unroll
                for (int t = 0; t < 2; t++) {
                    int idx = tid + t * 128;
                    int r = idx >> 2, sg = idx & 3;
                    cp16(su(Ks + kb * 2560 + r * 40 + sg * 8),
                         gk + (size_t)(n0 + r) * 32 + sg * 8);
                }
                cp_commit();
                cp_wait<1>();
            } else cp_wait<0>();
            bar384();
            if (nt == 0) {
#pragma unroll
                for (int mi = 0; mi < 2; mi++)
#pragma unroll
                    for (int kt = 0; kt < 2; kt++)
                        ldsm4(qa[mi][kt][0], qa[mi][kt][1], qa[mi][kt][2], qa[mi][kt][3],
                            su(Qs + (mt + mi * 16 + (lane & 15)) * 40 + kt * 16 + ((lane >> 4) << 3)));
            }
            float s[2][32];
#pragma unroll
            for (int mi = 0; mi < 2; mi++)
#pragma unroll
                for (int i = 0; i < 32; i++) s[mi][i] = 0.f;
            const __nv_bfloat16* Kb_ = Ks + buf * 2560;
#pragma unroll
            for (int jp = 0; jp < 4; jp++)
#pragma unroll
                for (int kt = 0; kt < 2; kt++) {
                    uint32_t r0, r1, r2, r3;
                    ldsm4(r0, r1, r2, r3,
                        su(Kb_ + (jp * 16 + (lane & 15)) * 40 + kt * 16 + ((lane >> 4) << 3)));
#pragma unroll
                    for (int mi = 0; mi < 2; mi++) {
                        mma16816(s[mi] + jp * 8,     qa[mi][kt], r0, r2);
                        mma16816(s[mi] + jp * 8 + 4, qa[mi][kt], r1, r3);
                    }
                }
            __nv_bfloat16* Pb = Ps + buf * 9216;
#pragma unroll
            for (int mi = 0; mi < 2; mi++) {
                __nv_bfloat16* pr = Pb + (mt + mi * 16 + (lane >> 2)) * 72 + (lane & 3) * 2;
#pragma unroll
                for (int j = 0; j < 8; j++) {
                    float p0 = ex2f(s[mi][j * 4 + 0]), p1 = ex2f(s[mi][j * 4 + 1]);
                    float p2 = ex2f(s[mi][j * 4 + 2]), p3 = ex2f(s[mi][j * 4 + 3]);
                    l4[mi * 2 + 0] += p0 + p1;
                    l4[mi * 2 + 1] += p2 + p3;
                    *(uint32_t*)(pr + j * 8)          = packbf2(p0, p1);
                    *(uint32_t*)(pr + 8 * 72 + j * 8) = packbf2(p2, p3);
                }
            }
        }
#pragma unroll
        for (int i = 0; i < 4; i++) {
            l4[i] += __shfl_xor_sync(~0u, l4[i], 1);
            l4[i] += __shfl_xor_sync(~0u, l4[i], 2);
        }
        if ((lane & 3) == 0) {
            Ls[mt + (lane >> 2)]      = l4[0];
            Ls[mt + 8 + (lane >> 2)]  = l4[1];
            Ls[mt + 16 + (lane >> 2)] = l4[2];
            Ls[mt + 24 + (lane >> 2)] = l4[3];
        }
        bar384();   // release P(63) + Ls to PV warps
    } else {
        // ------------------- PV warps -------------------
        const int pw = warp - 4;
        const int tid2 = tid - 128;
        float o[128];
#pragma unroll
        for (int i = 0; i < 128; i++) o[i] = 0.f;
#pragma unroll 1
        for (int nt = 0; nt <= 64; nt++) {
            if (nt + 1 < 64) {
                const int n0 = (nt + 1) * 64, vb = (nt + 1) % 3;
#pragma unroll
                for (int t = 0; t < 8; t++) {
                    int idx = tid2 + t * 256;
                    int c = idx >> 3, sg = idx & 7;
                    cp16(su(Vt + vb * 18432 + c * 72 + sg * 8),
                         gv + (size_t)c * NPIX + n0 + sg * 8);
                }
                cp_commit();
                cp_wait<1>();
            } else cp_wait<0>();
            bar384();
            if (nt == 0) continue;
            const int j = nt - 1, pbuf = j & 1, vbuf = j % 3;
            uint32_t pa[4][4];
            const __nv_bfloat16* Pb = Ps + pbuf * 9216;
#pragma unroll
            for (int kt = 0; kt < 4; kt++)
                ldsm4(pa[kt][0], pa[kt][1], pa[kt][2], pa[kt][3],
                    su(Pb + (pw * 16 + (lane & 15)) * 72 + kt * 16 + ((lane >> 4) << 3)));
            const __nv_bfloat16* Vb_ = Vt + vbuf * 18432;
#pragma unroll
            for (int cp = 0; cp < 16; cp++)
#pragma unroll
                for (int kt = 0; kt < 4; kt++) {
                    uint32_t v0, v1, v2, v3;
                    ldsm4(v0, v1, v2, v3,
                        su(Vb_ + (cp * 16 + (lane & 15)) * 72 + kt * 16 + ((lane >> 4) << 3)));
                    mma16816(o + cp * 8,     pa[kt], v0, v2);
                    mma16816(o + cp * 8 + 4, pa[kt], v1, v3);
                }
        }
        // epilogue: O/l * gamma + ef
        const float gm = gamma_p[0];
        const float inv0 = gm / Ls[pw * 16 + (lane >> 2)];
        const float inv1 = gm / Ls[pw * 16 + 8 + (lane >> 2)];
        const int r0 = m0 + pw * 16 + (lane >> 2);
#pragma unroll
        for (int cp = 0; cp < 16; cp++)
#pragma unroll
            for (int h = 0; h < 2; h++) {
                const int c = cp * 16 + h * 8 + (lane & 3) * 2;
                const int idx = cp * 8 + h * 4;
                size_t i00 = ((size_t)(b * 256 + c)) * NPIX + r0;
                size_t i01 = i00 + NPIX;
                out[i00]     = o[idx + 0] * inv0 + ef[i00];
                out[i01]     = o[idx + 1] * inv0 + ef[i01];
                out[i00 + 8] = o[idx + 2] * inv1 + ef[i00 + 8];
                out[i01 + 8] = o[idx + 3] * inv1 + ef[i01 + 8];
            }
    }
}

extern "C" void kernel_launch(void* const* d_in, const int* in_sizes, int n_in,
                              void* d_out, int out_size) {
    const float* ef = (const float*)d_in[0];
    const float* sf = (const float*)d_in[1];
    const float* At = (const float*)d_in[2];
    const float* Qw = (const float*)d_in[3];
    const float* Qb = (const float*)d_in[4];
    const float* Kw = (const float*)d_in[5];
    const float* Kb = (const float*)d_in[6];
    const float* Vw = (const float*)d_in[7];
    const float* Vb = (const float*)d_in[8];
    const float* gm = (const float*)d_in[9];
    float* out = (float*)d_out;

    cudaFuncSetAttribute(proj_kernel, cudaFuncAttributeMaxDynamicSharedMemorySize, PROJ_SMEM);
    cudaFuncSetAttribute(flash_kernel, cudaFuncAttributeMaxDynamicSharedMemorySize, FLASH_SMEM);

    proj_kernel<<<dim3(32, 4), 256, PROJ_SMEM>>>(ef, sf, At, Qw, Qb, Kw, Kb, Vw, Vb);
    flash_kernel<<<dim3(32, 4), 384, FLASH_SMEM>>>(ef, gm, out);
}

// round 17
// speedup vs baseline: 1.5887x; 1.5887x over previous
#include <cuda_runtime.h>
#include <cuda_bf16.h>
#include <cstdint>

constexpr int NPIX = 4096;
#define DEVI static __device__ __forceinline__

// bf16 scratch: q[B,N,32] (pre-scaled by log2e), k[B,N,32], v CHANNEL-MAJOR [B,256,N]
__device__ __nv_bfloat16 g_q[(size_t)4 * 4096 * 32];
__device__ __nv_bfloat16 g_k[(size_t)4 * 4096 * 32];
__device__ __nv_bfloat16 g_v[(size_t)4 * 256 * 4096];

DEVI uint32_t su(const void* p) { return (uint32_t)__cvta_generic_to_shared(p); }
DEVI void ldsm4(uint32_t& r0, uint32_t& r1, uint32_t& r2, uint32_t& r3, uint32_t a) {
    asm volatile("ldmatrix.sync.aligned.m8n8.x4.shared.b16 {%0,%1,%2,%3},[%4];"
                 : "=r"(r0), "=r"(r1), "=r"(r2), "=r"(r3) : "r"(a));
}
DEVI void ldsm4t(uint32_t& r0, uint32_t& r1, uint32_t& r2, uint32_t& r3, uint32_t a) {
    asm volatile("ldmatrix.sync.aligned.m8n8.x4.trans.shared.b16 {%0,%1,%2,%3},[%4];"
                 : "=r"(r0), "=r"(r1), "=r"(r2), "=r"(r3) : "r"(a));
}
DEVI void mma16816(float* c, const uint32_t* a, uint32_t b0, uint32_t b1) {
    asm volatile("mma.sync.aligned.m16n8k16.row.col.f32.bf16.bf16.f32 "
                 "{%0,%1,%2,%3},{%4,%5,%6,%7},{%8,%9},{%0,%1,%2,%3};"
                 : "+f"(c[0]), "+f"(c[1]), "+f"(c[2]), "+f"(c[3])
                 : "r"(a[0]), "r"(a[1]), "r"(a[2]), "r"(a[3]), "r"(b0), "r"(b1));
}
DEVI void cp16(uint32_t s, const void* g) {
    asm volatile("cp.async.cg.shared.global [%0],[%1],16;" ::"r"(s), "l"(g));
}
DEVI void cp_commit() { asm volatile("cp.async.commit_group;" ::: "memory"); }
template <int NN> DEVI void cp_wait() { asm volatile("cp.async.wait_group %0;" ::"n"(NN) : "memory"); }
DEVI float ex2f(float x) { float r; asm("ex2.approx.f32 %0,%1;" : "=f"(r) : "f"(x)); return r; }
DEVI uint32_t packbf2(float a, float b) {
    __nv_bfloat162 h = __floats2bfloat162_rn(a, b);
    return *reinterpret_cast<uint32_t*>(&h);
}
DEVI void bar384() { asm volatile("bar.sync 1, 384;" ::: "memory"); }

// ===========================================================================
// Projection, 256 threads / 8 warps (round-13 structure, inline weight
// conversion instead of prep kernel). block = (m-tile 128, batch).
// Writes q (log2e-scaled) / k row-major, v CHANNEL-MAJOR via smem transpose.
// smem: Xc[64][136], Ac[64][136], Wv[256][72], Wq[32][72], Wk[32][72]
// ===========================================================================
constexpr int PROJ_SMEM = (64 * 136 * 2) * 2 + 256 * 72 * 2 + 32 * 72 * 2 * 2;  // 80896

__global__ __launch_bounds__(256, 1) void proj_kernel(
    const float* __restrict__ ef, const float* __restrict__ sf, const float* __restrict__ attn,
    const float* __restrict__ Qw, const float* __restrict__ Qb,
    const float* __restrict__ Kw, const float* __restrict__ Kb,
    const float* __restrict__ Vw, const float* __restrict__ Vb)
{
    extern __shared__ __align__(16) char smem_raw[];
    __nv_bfloat16* Xc = (__nv_bfloat16*)smem_raw;
    __nv_bfloat16* Ac = Xc + 64 * 136;
    __nv_bfloat16* Wv = Ac + 64 * 136;
    __nv_bfloat16* Wq = Wv + 256 * 72;
    __nv_bfloat16* Wk = Wq + 32 * 72;

    const int b = blockIdx.y, m0 = blockIdx.x * 128;
    const int tid = threadIdx.x, lane = tid & 31, warp = tid >> 5, mw = warp * 16;
    const float L = 1.4426950408889634f;

    float ov[128], oq[16], ok[16];
#pragma unroll
    for (int i = 0; i < 128; i++) ov[i] = 0.f;
#pragma unroll
    for (int i = 0; i < 16; i++) { oq[i] = 0.f; ok[i] = 0.f; }

#pragma unroll 1
    for (int ic = 0; ic < 8; ic++) {
        const int i0 = ic * 64;
        __syncthreads();
        // ---- weights fp32 -> bf16 smem (inline conversion, no prep) ----
#pragma unroll
        for (int t = 0; t < 16; t++) {          // Vw chunk: 256 rows x 16 float4
            int idx = tid + t * 256, r = idx >> 4, j4 = (idx & 15) * 4;
            float4 v = *(const float4*)(Vw + (size_t)r * 512 + i0 + j4);
            *(uint2*)(Wv + r * 72 + j4) = make_uint2(packbf2(v.x, v.y), packbf2(v.z, v.w));
        }
        for (int t = tid; t < 32 * 16; t += 256) {   // Qw chunk (log2e-scaled)
            int r = t >> 4, j4 = (t & 15) * 4;
            float4 v = *(const float4*)(Qw + (size_t)r * 512 + i0 + j4);
            *(uint2*)(Wq + r * 72 + j4) =
                make_uint2(packbf2(v.x * L, v.y * L), packbf2(v.z * L, v.w * L));
        }
        if (ic < 4) {
            for (int t = tid; t < 32 * 16; t += 256) {
                int r = t >> 4, j4 = (t & 15) * 4;
                float4 v = *(const float4*)(Kw + (size_t)r * 256 + i0 + j4);
                *(uint2*)(Wk + r * 72 + j4) = make_uint2(packbf2(v.x, v.y), packbf2(v.z, v.w));
            }
        }
        // ---- X chunk [64 i][128 m] fp32 -> bf16 ----
#pragma unroll
        for (int t = 0; t < 8; t++) {
            int idx = tid + t * 256, il = idx >> 5, j = (idx & 31) * 4;
            int gi = i0 + il;
            const float* src = (gi < 256) ? (ef + ((size_t)(b * 256 + gi)) * NPIX + m0 + j)
                                          : (sf + ((size_t)(b * 256 + gi - 256)) * NPIX + m0 + j);
            float4 v = *(const float4*)src;
            *(uint2*)(Xc + il * 136 + j) = make_uint2(packbf2(v.x, v.y), packbf2(v.z, v.w));
        }
        if (ic < 4) {
#pragma unroll
            for (int t = 0; t < 8; t++) {
                int idx = tid + t * 256, il = idx >> 5, j = (idx & 31) * 4;
                float4 v = *(const float4*)(attn + ((size_t)(b * 256 + i0 + il)) * NPIX + m0 + j);
                *(uint2*)(Ac + il * 136 + j) = make_uint2(packbf2(v.x, v.y), packbf2(v.z, v.w));
            }
        }
        __syncthreads();

#pragma unroll
        for (int kt = 0; kt < 4; kt++) {
            const int k0 = kt * 16;
            uint32_t xa[4];
            ldsm4t(xa[0], xa[1], xa[2], xa[3],
                su(Xc + (k0 + (lane & 7) + ((lane >> 4) << 3)) * 136 + mw + (((lane >> 3) & 1) << 3)));
#pragma unroll
            for (int cp = 0; cp < 16; cp++) {
                uint32_t b0, b1, b2, b3;
                ldsm4(b0, b1, b2, b3, su(Wv + ((cp << 4) + (lane & 15)) * 72 + k0 + ((lane >> 4) << 3)));
                mma16816(ov + cp * 8, xa, b0, b2);
                mma16816(ov + cp * 8 + 4, xa, b1, b3);
            }
            {
                uint32_t b0, b1, b2, b3;
                ldsm4(b0, b1, b2, b3, su(Wq + (lane & 15) * 72 + k0 + ((lane >> 4) << 3)));
                mma16816(oq + 0, xa, b0, b2);
                mma16816(oq + 4, xa, b1, b3);
                ldsm4(b0, b1, b2, b3, su(Wq + (16 + (lane & 15)) * 72 + k0 + ((lane >> 4) << 3)));
                mma16816(oq + 8, xa, b0, b2);
                mma16816(oq + 12, xa, b1, b3);
            }
            if (ic < 4) {
                uint32_t aa[4];
                ldsm4t(aa[0], aa[1], aa[2], aa[3],
                    su(Ac + (k0 + (lane & 7) + ((lane >> 4) << 3)) * 136 + mw + (((lane >> 3) & 1) << 3)));
                uint32_t b0, b1, b2, b3;
                ldsm4(b0, b1, b2, b3, su(Wk + (lane & 15) * 72 + k0 + ((lane >> 4) << 3)));
                mma16816(ok + 0, aa, b0, b2);
                mma16816(ok + 4, aa, b1, b3);
                ldsm4(b0, b1, b2, b3, su(Wk + (16 + (lane & 15)) * 72 + k0 + ((lane >> 4) << 3)));
                mma16816(ok + 8, aa, b0, b2);
                mma16816(ok + 12, aa, b1, b3);
            }
        }
    }

    const int r0 = m0 + mw + (lane >> 2), cb = (lane & 3) * 2;
#pragma unroll
    for (int dt = 0; dt < 4; dt++) {
        int d = dt * 8 + cb;
        float bq0 = Qb[d] * L, bq1 = Qb[d + 1] * L;
        *(uint32_t*)&g_q[((size_t)(b * NPIX + r0)) * 32 + d]     = packbf2(oq[dt * 4 + 0] + bq0, oq[dt * 4 + 1] + bq1);
        *(uint32_t*)&g_q[((size_t)(b * NPIX + r0 + 8)) * 32 + d] = packbf2(oq[dt * 4 + 2] + bq0, oq[dt * 4 + 3] + bq1);
        float bk0 = Kb[d], bk1 = Kb[d + 1];
        *(uint32_t*)&g_k[((size_t)(b * NPIX + r0)) * 32 + d]     = packbf2(ok[dt * 4 + 0] + bk0, ok[dt * 4 + 1] + bk1);
        *(uint32_t*)&g_k[((size_t)(b * NPIX + r0 + 8)) * 32 + d] = packbf2(ok[dt * 4 + 2] + bk0, ok[dt * 4 + 3] + bk1);
    }
    // v: transpose through smem -> channel-major g_v[b][c][m]
    __syncthreads();
    __nv_bfloat16* Vt = (__nv_bfloat16*)smem_raw;   // [256][136]
    const int rl = mw + (lane >> 2);
#pragma unroll
    for (int ct = 0; ct < 32; ct++) {
        int c = ct * 8 + cb;
        float bb0 = Vb[c], bb1 = Vb[c + 1];
        Vt[c * 136 + rl]           = __float2bfloat16(ov[ct * 4 + 0] + bb0);
        Vt[(c + 1) * 136 + rl]     = __float2bfloat16(ov[ct * 4 + 1] + bb1);
        Vt[c * 136 + rl + 8]       = __float2bfloat16(ov[ct * 4 + 2] + bb0);
        Vt[(c + 1) * 136 + rl + 8] = __float2bfloat16(ov[ct * 4 + 3] + bb1);
    }
    __syncthreads();
#pragma unroll
    for (int t = 0; t < 16; t++) {
        int i = tid + t * 256;                 // 4096 uint4 = 256 rows x 16
        int c = i >> 4, seg = i & 15;
        *(uint4*)(g_v + ((size_t)(b * 256 + c)) * NPIX + m0 + seg * 8) =
            *(uint4*)(Vt + c * 136 + seg * 8);
    }
}

// ===========================================================================
// Flash attention (round-10 winner, EXACT): warp-specialized HMMA.
// 384 threads: warps 0-3 = S (QK^T + exp2 -> P smem + row sums)
//              warps 4-11 = PV (O[16m x 256ch] fp32 regs)
// smem: Qs[128][40] | Ks[2][64][40] | Vt[3][256][72] | Ps[2][128][72] | Ls[128]
// ===========================================================================
constexpr int FS_Q = 0;
constexpr int FS_K = FS_Q + 128 * 40 * 2;           // 10240
constexpr int FS_V = FS_K + 2 * 64 * 40 * 2;        // 20480
constexpr int FS_P = FS_V + 3 * 256 * 72 * 2;       // 131072
constexpr int FS_L = FS_P + 2 * 128 * 72 * 2;       // 167936
constexpr int FLASH_SMEM = FS_L + 512;              // 168448

__global__ __launch_bounds__(384, 1)
void flash_kernel(const float* __restrict__ ef, const float* __restrict__ gamma_p,
                  float* __restrict__ out)
{
    extern __shared__ __align__(16) char smem[];
    __nv_bfloat16* Qs = (__nv_bfloat16*)(smem + FS_Q);
    __nv_bfloat16* Ks = (__nv_bfloat16*)(smem + FS_K);
    __nv_bfloat16* Vt = (__nv_bfloat16*)(smem + FS_V);
    __nv_bfloat16* Ps = (__nv_bfloat16*)(smem + FS_P);
    float* Ls = (float*)(smem + FS_L);

    const int b = blockIdx.y, m0 = blockIdx.x * 128;
    const int tid = threadIdx.x, lane = tid & 31, warp = tid >> 5;

    const __nv_bfloat16* gq = g_q + (size_t)b * NPIX * 32;
    const __nv_bfloat16* gk = g_k + (size_t)b * NPIX * 32;
    const __nv_bfloat16* gv = g_v + (size_t)b * 256 * NPIX;   // [256][4096]

    // initial loads: Q (full), K(0), V(0)
#pragma unroll
    for (int t = 0; t < 2; t++) {
        int idx = tid + t * 384;
        if (idx < 512) {
            int r = idx >> 2, sg = idx & 3;
            cp16(su(Qs + r * 40 + sg * 8), gq + (size_t)(m0 + r) * 32 + sg * 8);
        }
    }
    if (tid < 256) {
        int r = tid >> 2, sg = tid & 3;
        cp16(su(Ks + r * 40 + sg * 8), gk + (size_t)r * 32 + sg * 8);
    }
#pragma unroll
    for (int t = 0; t < 6; t++) {
        int idx = tid + t * 384;
        if (idx < 2048) {
            int c = idx >> 3, sg = idx & 7;
            cp16(su(Vt + c * 72 + sg * 8), gv + (size_t)c * NPIX + sg * 8);
        }
    }
    cp_commit();

    if (warp < 4) {
        // ------------------- S warps -------------------
        const int mt = warp * 32;
        uint32_t qa[2][2][4];
        float l4[4] = {0.f, 0.f, 0.f, 0.f};
#pragma unroll 1
        for (int nt = 0; nt < 64; nt++) {
            const int buf = nt & 1;
            if (nt + 1 < 64) {
                const int n0 = (nt + 1) * 64, kb = (nt + 1) & 1;
#pragma unroll
                for (int t = 0; t < 2; t++) {
                    int idx = tid + t * 128;
                    int r = idx >> 2, sg = idx & 3;
                    cp16(su(Ks + kb * 2560 + r * 40 + sg * 8),
                         gk + (size_t)(n0 + r) * 32 + sg * 8);
                }
                cp_commit();
                cp_wait<1>();
            } else cp_wait<0>();
            bar384();
            if (nt == 0) {
#pragma unroll
                for (int mi = 0; mi < 2; mi++)
#pragma unroll
                    for (int kt = 0; kt < 2; kt++)
                        ldsm4(qa[mi][kt][0], qa[mi][kt][1], qa[mi][kt][2], qa[mi][kt][3],
                            su(Qs + (mt + mi * 16 + (lane & 15)) * 40 + kt * 16 + ((lane >> 4) << 3)));
            }
            float s[2][32];
#pragma unroll
            for (int mi = 0; mi < 2; mi++)
#pragma unroll
                for (int i = 0; i < 32; i++) s[mi][i] = 0.f;
            const __nv_bfloat16* Kb_ = Ks + buf * 2560;
#pragma unroll
            for (int jp = 0; jp < 4; jp++)
#pragma unroll
                for (int kt = 0; kt < 2; kt++) {
                    uint32_t r0, r1, r2, r3;
                    ldsm4(r0, r1, r2, r3,
                        su(Kb_ + (jp * 16 + (lane & 15)) * 40 + kt * 16 + ((lane >> 4) << 3)));
#pragma unroll
                    for (int mi = 0; mi < 2; mi++) {
                        mma16816(s[mi] + jp * 8,     qa[mi][kt], r0, r2);
                        mma16816(s[mi] + jp * 8 + 4, qa[mi][kt], r1, r3);
                    }
                }
            __nv_bfloat16* Pb = Ps + buf * 9216;
#pragma unroll
            for (int mi = 0; mi < 2; mi++) {
                __nv_bfloat16* pr = Pb + (mt + mi * 16 + (lane >> 2)) * 72 + (lane & 3) * 2;
#pragma unroll
                for (int j = 0; j < 8; j++) {
                    float p0 = ex2f(s[mi][j * 4 + 0]), p1 = ex2f(s[mi][j * 4 + 1]);
                    float p2 = ex2f(s[mi][j * 4 + 2]), p3 = ex2f(s[mi][j * 4 + 3]);
                    l4[mi * 2 + 0] += p0 + p1;
                    l4[mi * 2 + 1] += p2 + p3;
                    *(uint32_t*)(pr + j * 8)          = packbf2(p0, p1);
                    *(uint32_t*)(pr + 8 * 72 + j * 8) = packbf2(p2, p3);
                }
            }
        }
#pragma unroll
        for (int i = 0; i < 4; i++) {
            l4[i] += __shfl_xor_sync(~0u, l4[i], 1);
            l4[i] += __shfl_xor_sync(~0u, l4[i], 2);
        }
        if ((lane & 3) == 0) {
            Ls[mt + (lane >> 2)]      = l4[0];
            Ls[mt + 8 + (lane >> 2)]  = l4[1];
            Ls[mt + 16 + (lane >> 2)] = l4[2];
            Ls[mt + 24 + (lane >> 2)] = l4[3];
        }
        bar384();   // release P(63) + Ls to PV warps
    } else {
        // ------------------- PV warps -------------------
        const int pw = warp - 4;
        const int tid2 = tid - 128;
        float o[128];
#pragma unroll
        for (int i = 0; i < 128; i++) o[i] = 0.f;
#pragma unroll 1
        for (int nt = 0; nt <= 64; nt++) {
            if (nt + 1 < 64) {
                const int n0 = (nt + 1) * 64, vb = (nt + 1) % 3;
#pragma unroll
                for (int t = 0; t < 8; t++) {
                    int idx = tid2 + t * 256;
                    int c = idx >> 3, sg = idx & 7;
                    cp16(su(Vt + vb * 18432 + c * 72 + sg * 8),
                         gv + (size_t)c * NPIX + n0 + sg * 8);
                }
                cp_commit();
                cp_wait<1>();
            } else cp_wait<0>();
            bar384();
            if (nt == 0) continue;
            const int j = nt - 1, pbuf = j & 1, vbuf = j % 3;
            uint32_t pa[4][4];
            const __nv_bfloat16* Pb = Ps + pbuf * 9216;
#pragma unroll
            for (int kt = 0; kt < 4; kt++)
                ldsm4(pa[kt][0], pa[kt][1], pa[kt][2], pa[kt][3],
                    su(Pb + (pw * 16 + (lane & 15)) * 72 + kt * 16 + ((lane >> 4) << 3)));
            const __nv_bfloat16* Vb_ = Vt + vbuf * 18432;
#pragma unroll
            for (int cp = 0; cp < 16; cp++)
#pragma unroll
                for (int kt = 0; kt < 4; kt++) {
                    uint32_t v0, v1, v2, v3;
                    ldsm4(v0, v1, v2, v3,
                        su(Vb_ + (cp * 16 + (lane & 15)) * 72 + kt * 16 + ((lane >> 4) << 3)));
                    mma16816(o + cp * 8,     pa[kt], v0, v2);
                    mma16816(o + cp * 8 + 4, pa[kt], v1, v3);
                }
        }
        // epilogue: O/l * gamma + ef
        const float gm = gamma_p[0];
        const float inv0 = gm / Ls[pw * 16 + (lane >> 2)];
        const float inv1 = gm / Ls[pw * 16 + 8 + (lane >> 2)];
        const int r0 = m0 + pw * 16 + (lane >> 2);
#pragma unroll
        for (int cp = 0; cp < 16; cp++)
#pragma unroll
            for (int h = 0; h < 2; h++) {
                const int c = cp * 16 + h * 8 + (lane & 3) * 2;
                const int idx = cp * 8 + h * 4;
                size_t i00 = ((size_t)(b * 256 + c)) * NPIX + r0;
                size_t i01 = i00 + NPIX;
                out[i00]     = o[idx + 0] * inv0 + ef[i00];
                out[i01]     = o[idx + 1] * inv0 + ef[i01];
                out[i00 + 8] = o[idx + 2] * inv1 + ef[i00 + 8];
                out[i01 + 8] = o[idx + 3] * inv1 + ef[i01 + 8];
            }
    }
}

extern "C" void kernel_launch(void* const* d_in, const int* in_sizes, int n_in,
                              void* d_out, int out_size) {
    const float* ef = (const float*)d_in[0];
    const float* sf = (const float*)d_in[1];
    const float* At = (const float*)d_in[2];
    const float* Qw = (const float*)d_in[3];
    const float* Qb = (const float*)d_in[4];
    const float* Kw = (const float*)d_in[5];
    const float* Kb = (const float*)d_in[6];
    const float* Vw = (const float*)d_in[7];
    const float* Vb = (const float*)d_in[8];
    const float* gm = (const float*)d_in[9];
    float* out = (float*)d_out;

    cudaFuncSetAttribute(proj_kernel, cudaFuncAttributeMaxDynamicSharedMemorySize, PROJ_SMEM);
    cudaFuncSetAttribute(flash_kernel, cudaFuncAttributeMaxDynamicSharedMemorySize, FLASH_SMEM);

    proj_kernel<<<dim3(32, 4), 256, PROJ_SMEM>>>(ef, sf, At, Qw, Qb, Kw, Kb, Vw, Vb);
    flash_kernel<<<dim3(32, 4), 384, FLASH_SMEM>>>(ef, gm, out);
}